// round 11
// baseline (speedup 1.0000x reference)
#include <cuda_runtime.h>
#include <cstdint>

#define B_ 2
#define H_ 8
#define S_ 1024
#define DK_ 64
#define DV_ 64
static constexpr float INV_T = 0.125f;                   // 1/temperature
static constexpr int OUT_ATTN_OFF = B_ * H_ * S_ * DV_;  // 1048576

// ---- packed fp32 helpers (sm_103a f32x2 pipe) -------------------------------
#define FMA2(acc, a, b) asm("fma.rn.f32x2 %0, %1, %2, %0;" : "+l"(acc) : "l"(a), "l"(b))

__device__ __forceinline__ float2 unpack2(unsigned long long v) {
    float2 r;
    asm("mov.b64 {%0, %1}, %2;" : "=f"(r.x), "=f"(r.y) : "l"(v));
    return r;
}

// ---- cp.async helpers -------------------------------------------------------
__device__ __forceinline__ uint32_t s2u(const void* p) {
    return (uint32_t)__cvta_generic_to_shared(p);
}
__device__ __forceinline__ void cp8(uint32_t dst, const void* src) {
    asm volatile("cp.async.ca.shared.global [%0], [%1], 8;" :: "r"(dst), "l"(src));
}
__device__ __forceinline__ void cp16(uint32_t dst, const void* src) {
    asm volatile("cp.async.cg.shared.global [%0], [%1], 16;" :: "r"(dst), "l"(src));
}
#define CP_COMMIT() asm volatile("cp.async.commit_group;")
#define CP_WAIT0()  asm volatile("cp.async.wait_group 0;")
#define CP_WAIT1()  asm volatile("cp.async.wait_group 1;")
#define CP_WAIT2()  asm volatile("cp.async.wait_group 2;")
#define CP_WAIT3()  asm volatile("cp.async.wait_group 3;")

// ---------------------------------------------------------------------------
// K1 (measured 52us, 60% FMA2 ceiling): attn1 = (q/T).k^T, d-parity packing.
// Tile 128i x 64j, 256 threads, 8x4 micro (j strided by 16). UNCHANGED.
// ---------------------------------------------------------------------------
static constexpr int K1_PITCH = 66;
static constexpr int K1_SMEM = (128 + 64) * K1_PITCH * 4;   // 50688 B

__global__ void __launch_bounds__(256, 2) k1_qk(const float* __restrict__ q,
                                                const float* __restrict__ k,
                                                float* __restrict__ attn)
{
    extern __shared__ float sm1[];
    float* Qs = sm1;                    // [128][66]
    float* Ks = sm1 + 128 * K1_PITCH;   // [64][66]

    const int bh = blockIdx.z;
    const int i0 = blockIdx.y * 128;
    const int j0 = blockIdx.x * 64;
    const float* qb = q + ((size_t)bh * S_ + i0) * DK_;
    const float* kb = k + ((size_t)bh * S_ + j0) * DK_;
    const int t = threadIdx.x;
    const uint32_t qs_u = s2u(Qs), ks_u = s2u(Ks);

    #pragma unroll
    for (int m = 0; m < 16; m++) {
        const int idx = m * 256 + t;
        const int row = idx >> 5, p = idx & 31;
        cp8(qs_u + (uint32_t)(row * K1_PITCH + 2 * p) * 4u, qb + (size_t)idx * 2);
    }
    #pragma unroll
    for (int m = 0; m < 8; m++) {
        const int idx = m * 256 + t;
        const int row = idx >> 5, p = idx & 31;
        cp8(ks_u + (uint32_t)(row * K1_PITCH + 2 * p) * 4u, kb + (size_t)idx * 2);
    }
    CP_COMMIT();
    CP_WAIT0();
    __syncthreads();

    const int tx = t & 15;
    const int ty = t >> 4;
    const float* qp = Qs + (ty * 8) * K1_PITCH;
    const float* kp = Ks + tx * K1_PITCH;

    unsigned long long acc[8][4] = {};

    #pragma unroll 8
    for (int dp = 0; dp < 32; dp++) {
        unsigned long long kv[4], qv[8];
        #pragma unroll
        for (int s = 0; s < 4; s++)
            kv[s] = *(const unsigned long long*)(kp + (16 * s) * K1_PITCH + 2 * dp);
        #pragma unroll
        for (int r = 0; r < 8; r++)
            qv[r] = *(const unsigned long long*)(qp + r * K1_PITCH + 2 * dp);
        #pragma unroll
        for (int r = 0; r < 8; r++)
            #pragma unroll
            for (int s = 0; s < 4; s++)
                FMA2(acc[r][s], qv[r], kv[s]);
    }

    #pragma unroll
    for (int r = 0; r < 8; r++) {
        float* row = attn + (((size_t)bh * S_ + i0 + ty * 8 + r) * S_) + j0;
        #pragma unroll
        for (int s = 0; s < 4; s++) {
            float2 pv = unpack2(acc[r][s]);
            row[tx + 16 * s] = (pv.x + pv.y) * INV_T;
        }
    }
}

// ---------------------------------------------------------------------------
// K2 (NEW pipeline): per (b,i): logits[h][j] = attn1 + qs.rpr; mask; softmax.
// Chunk 64 j, 4-deep cp16 buffer ring (wait_group 3) -> ~3 chunks of DRAM
// lead always in flight. Head groups of 2 (g = t>>6), d-parity inner loop
// (zero dup2). Logits in regs (l[2][16]); block softmax; 2 CTAs/SM.
// ---------------------------------------------------------------------------
static constexpr int K2_CHUNK = 64;
static constexpr int K2_PITCH = 68;                      // 16B rows, xbar-clean
static constexpr int K2_BUF = K2_CHUNK * K2_PITCH;       // 4352 floats
static constexpr int K2_SMEM = (512 + 64 + 4 * K2_BUF) * 4;  // 71936 B

__device__ __forceinline__ void k2_stage(uint32_t rs_u, const float* __restrict__ src,
                                         int t)
{
    // 64 rows x 16 float4 = 1024 cp16; 4 per thread, coalesced
    #pragma unroll
    for (int m = 0; m < 4; m++) {
        const int idx = m * 256 + t;
        const int row = idx >> 4;
        const int gg  = idx & 15;
        cp16(rs_u + (uint32_t)(row * K2_PITCH + 4 * gg) * 4u, src + (size_t)idx * 4);
    }
    CP_COMMIT();
}

__global__ void __launch_bounds__(256, 2) k2_rpr_softmax(
    const float* __restrict__ q,
    const float* __restrict__ rpr,
    const int* __restrict__ mask,
    float* __restrict__ attn)
{
    extern __shared__ float sm2[];
    float* qs3   = sm2;             // [32 dp][8 h][2 e] = 512
    float* redmx = sm2 + 512;       // [8 h][2 warps]
    float* redsm = sm2 + 528;       // [8 h][2 warps]
    float* bufs  = sm2 + 576;       // 4 x [64][68]

    const int b = blockIdx.y;
    const int i = blockIdx.x;
    const int t = threadIdx.x;
    const int g  = t >> 6;          // head group: heads 2g, 2g+1
    const int hb = g * 2;
    const int jl = t & 63;
    const int w = t >> 5, lane = t & 31;

    const float* rbase = rpr + ((size_t)b * S_ + i) * S_ * DK_;
    const int* mrow = mask + ((size_t)b * S_ + i) * S_;
    uint32_t ru[4];
    const float* rp[4];
    #pragma unroll
    for (int n = 0; n < 4; n++) {
        rp[n] = bufs + n * K2_BUF;
        ru[n] = s2u(rp[n]);
    }

    // prologue: 3 chunks in flight
    k2_stage(ru[0], rbase, t);
    k2_stage(ru[1], rbase + (size_t)K2_CHUNK * DK_, t);
    k2_stage(ru[2], rbase + (size_t)2 * K2_CHUNK * DK_, t);

    // qs3[dp][h][e] = q[b,h,i,2dp+e]/T  (overlaps the staging)
    #pragma unroll
    for (int idx = t; idx < 512; idx += 256) {
        const int e = idx & 1, h = (idx >> 1) & 7, dp = idx >> 4;
        qs3[idx] = q[(((size_t)b * H_ + h) * S_ + i) * DK_ + 2 * dp + e] * INV_T;
    }

    float l[2][16];                 // [head-in-group][chunk]

    #pragma unroll
    for (int c = 0; c < 16; c++) {
        if (c) __syncthreads();     // readers of buf[(c+3)&3] (iter c-1) done

        const int j = c * K2_CHUNK + jl;
        const int mk = mrow[j];
        float a1v[2];               // attn1 prefetch (overlaps cp.async)
        a1v[0] = attn[(((size_t)b * H_ + hb)     * S_ + i) * S_ + j];
        a1v[1] = attn[(((size_t)b * H_ + hb + 1) * S_ + i) * S_ + j];

        if (c < 13) {               // keep 3 chunks of lead in flight
            k2_stage(ru[(c + 3) & 3], rbase + (size_t)(c + 3) * K2_CHUNK * DK_, t);
            CP_WAIT3();
        } else if (c == 13) {
            CP_WAIT2();
        } else if (c == 14) {
            CP_WAIT1();
        } else {
            CP_WAIT0();
        }
        __syncthreads();            // all threads' copies of buf[c&3] visible

        unsigned long long acc[2] = {};      // 2 heads, packed (even-d, odd-d)
        const float* rr = rp[c & 3] + jl * K2_PITCH;
        #pragma unroll
        for (int gg = 0; gg < 16; gg++) {
            ulonglong2 rpv = *(const ulonglong2*)(rr + 4 * gg);  // dp=2gg, 2gg+1
            const float* qb0 = qs3 + (2 * gg) * 16 + hb * 2;
            ulonglong2 qA = *(const ulonglong2*)(qb0);           // dp0: h hb,hb+1
            ulonglong2 qC = *(const ulonglong2*)(qb0 + 16);      // dp1: h hb,hb+1
            FMA2(acc[0], qA.x, rpv.x);
            FMA2(acc[1], qA.y, rpv.x);
            FMA2(acc[0], qC.x, rpv.y);
            FMA2(acc[1], qC.y, rpv.y);
        }
        #pragma unroll
        for (int hh = 0; hh < 2; hh++) {
            float2 pv = unpack2(acc[hh]);
            l[hh][c] = mk ? (pv.x + pv.y + a1v[hh]) : -1e9f;
        }
    }

    // ---- block softmax: head h lives on 2 warps ----
    #pragma unroll
    for (int hh = 0; hh < 2; hh++) {
        float m = l[hh][0];
        #pragma unroll
        for (int c = 1; c < 16; c++) m = fmaxf(m, l[hh][c]);
        #pragma unroll
        for (int o = 16; o > 0; o >>= 1)
            m = fmaxf(m, __shfl_xor_sync(0xffffffffu, m, o));
        if (lane == 0) redmx[(hb + hh) * 2 + (w & 1)] = m;
    }
    __syncthreads();
    float mx[2];
    #pragma unroll
    for (int hh = 0; hh < 2; hh++) {
        const float* p = redmx + (hb + hh) * 2;
        mx[hh] = fmaxf(p[0], p[1]);
    }
    #pragma unroll
    for (int hh = 0; hh < 2; hh++) {
        float s = 0.f;
        #pragma unroll
        for (int c = 0; c < 16; c++) {
            l[hh][c] = __expf(l[hh][c] - mx[hh]);
            s += l[hh][c];
        }
        #pragma unroll
        for (int o = 16; o > 0; o >>= 1)
            s += __shfl_xor_sync(0xffffffffu, s, o);
        if (lane == 0) redsm[(hb + hh) * 2 + (w & 1)] = s;
    }
    __syncthreads();
    #pragma unroll
    for (int hh = 0; hh < 2; hh++) {
        const float* p = redsm + (hb + hh) * 2;
        const float rinv = 1.0f / (p[0] + p[1]);
        float* arow = attn + (((size_t)b * H_ + hb + hh) * S_ + i) * S_;
        #pragma unroll
        for (int c = 0; c < 16; c++)
            arow[c * K2_CHUNK + jl] = l[hh][c] * rinv;
    }
}

// ---------------------------------------------------------------------------
// K3 (retuned): output[b,h,i,:] = sum_j attn[b,h,i,j] * v[b,h,j,:]
// j-parity packing with transposed V (Vt[n][j], pitch 66). Tile 64i x 64n
// -> grid 256, 2 CTAs/SM (16 warps/SM). 4x4 micro (n strided by 16),
// j chunks of 64, double-buffered (As via cp8, V via LDG prefetch + STS).
// ---------------------------------------------------------------------------
static constexpr int K3_PITCH = 66;
static constexpr int K3_AS = 64 * K3_PITCH;                  // 4224 floats
static constexpr int K3_VT = 64 * K3_PITCH;                  // 4224 floats
static constexpr int K3_SMEM = 2 * (K3_AS + K3_VT) * 4;      // 67584 B

__device__ __forceinline__ void k3_stage_as(uint32_t as_u, const float* __restrict__ ab,
                                            int jc, int t)
{
    // As[row][0..63] <- attn[i0+row][jc..jc+63]; 2048 cp8, 8/thread, coalesced
    #pragma unroll
    for (int m = 0; m < 8; m++) {
        const int idx = m * 256 + t;
        const int row = idx >> 5, p = idx & 31;
        cp8(as_u + (uint32_t)(row * K3_PITCH + 2 * p) * 4u,
            ab + (size_t)row * S_ + jc + 2 * p);
    }
    CP_COMMIT();
}

__global__ void __launch_bounds__(256, 2) k3_av(const float* __restrict__ attn,
                                                const float* __restrict__ v,
                                                float* __restrict__ out)
{
    extern __shared__ float sm3[];
    float* Asb[2] = { sm3,                     sm3 + (K3_AS + K3_VT) };
    float* Vtb[2] = { sm3 + K3_AS,             sm3 + (K3_AS + K3_VT) + K3_AS };

    const int bh = blockIdx.y;
    const int i0 = blockIdx.x * 64;
    const int t = threadIdx.x;
    const int tx = t & 15;       // n slots: tx + 16s
    const int ty = t >> 4;       // i rows: ty*4 + r
    const float* ab = attn + ((size_t)bh * S_ + i0) * S_;
    const float* vb = v + (size_t)bh * S_ * DV_;
    const uint32_t as_u[2] = { s2u(Asb[0]), s2u(Asb[1]) };

    unsigned long long acc[4][4] = {};   // [i-row r][n-slot s], packed (ej, oj)

    // prologue: prefetch v chunk 0 into regs, As chunk 0 in flight
    float4 vreg[4];
    #pragma unroll
    for (int m = 0; m < 4; m++) {
        const int idx = m * 256 + t;
        vreg[m] = *(const float4*)(vb + (size_t)(idx >> 4) * DV_ + (idx & 15) * 4);
    }
    k3_stage_as(as_u[0], ab, 0, t);

    for (int c = 0; c < 16; c++) {
        const int cur = c & 1;
        CP_WAIT0();                      // As(c) resident

        // transpose-store v chunk c: Vt[n][j]
        float* Vt = Vtb[cur];
        #pragma unroll
        for (int m = 0; m < 4; m++) {
            const int idx = m * 256 + t;
            const int vr = idx >> 4;      // j within chunk
            const int vc = idx & 15;      // n group
            Vt[(4 * vc + 0) * K3_PITCH + vr] = vreg[m].x;
            Vt[(4 * vc + 1) * K3_PITCH + vr] = vreg[m].y;
            Vt[(4 * vc + 2) * K3_PITCH + vr] = vreg[m].z;
            Vt[(4 * vc + 3) * K3_PITCH + vr] = vreg[m].w;
        }
        __syncthreads();                 // As(c) + Vt(c) visible to all

        if (c < 15) {                    // next chunk in flight during compute
            #pragma unroll
            for (int m = 0; m < 4; m++) {
                const int idx = m * 256 + t;
                vreg[m] = *(const float4*)(vb + (size_t)((c + 1) * 64 + (idx >> 4)) * DV_
                                           + (idx & 15) * 4);
            }
            k3_stage_as(as_u[cur ^ 1], ab, (c + 1) * 64, t);
        }

        const float* ap = Asb[cur] + (ty * 4) * K3_PITCH;
        const float* vp = Vt + tx * K3_PITCH;
        #pragma unroll 8
        for (int jp = 0; jp < 32; jp++) {
            unsigned long long vv[4], av[4];
            #pragma unroll
            for (int s = 0; s < 4; s++)
                vv[s] = *(const unsigned long long*)(vp + (16 * s) * K3_PITCH + 2 * jp);
            #pragma unroll
            for (int r = 0; r < 4; r++)
                av[r] = *(const unsigned long long*)(ap + r * K3_PITCH + 2 * jp);
            #pragma unroll
            for (int r = 0; r < 4; r++)
                #pragma unroll
                for (int s = 0; s < 4; s++)
                    FMA2(acc[r][s], av[r], vv[s]);
        }
        __syncthreads();                 // buf consumed before restage at c+2
    }

    #pragma unroll
    for (int r = 0; r < 4; r++) {
        float* orow = out + ((size_t)bh * S_ + i0 + ty * 4 + r) * DV_;
        #pragma unroll
        for (int s = 0; s < 4; s++) {
            float2 pv = unpack2(acc[r][s]);
            orow[tx + 16 * s] = pv.x + pv.y;
        }
    }
}

// ---------------------------------------------------------------------------
extern "C" void kernel_launch(void* const* d_in, const int* in_sizes, int n_in,
                              void* d_out, int out_size)
{
    const float* q    = (const float*)d_in[0];
    const float* k    = (const float*)d_in[1];
    const float* v    = (const float*)d_in[2];
    const int*   mask = (const int*)d_in[3];
    const float* rpr  = (const float*)d_in[4];
    float* out  = (float*)d_out;
    float* attn = out + OUT_ATTN_OFF;

    cudaFuncSetAttribute(k1_qk, cudaFuncAttributeMaxDynamicSharedMemorySize, K1_SMEM);
    cudaFuncSetAttribute(k2_rpr_softmax, cudaFuncAttributeMaxDynamicSharedMemorySize,
                         K2_SMEM);
    cudaFuncSetAttribute(k3_av, cudaFuncAttributeMaxDynamicSharedMemorySize, K3_SMEM);

    {   // K1: attn1 logits into attn region (scratch, rewritten by K2)
        dim3 grid(S_ / 64, S_ / 128, B_ * H_);
        k1_qk<<<grid, 256, K1_SMEM>>>(q, k, attn);
    }
    {   // K2: + positional term, mask, softmax
        dim3 grid(S_, B_);
        k2_rpr_softmax<<<grid, 256, K2_SMEM>>>(q, rpr, mask, attn);
    }
    {   // K3: output = attn @ v
        dim3 grid(S_ / 64, B_ * H_);
        k3_av<<<grid, 256, K3_SMEM>>>(attn, v, out);
    }
}